// round 2
// baseline (speedup 1.0000x reference)
#include <cuda_runtime.h>
#include <cuda_bf16.h>

#define NNODES 50000
#define NEDGES 800000
#define CDIM 256
#define FIN 768

// Scratch (allocation-free rule: device globals)
__device__ float g_dinv[NNODES];
__device__ int   g_deg[NNODES];
__device__ float g_hs [NNODES * CDIM];   // row-scaled GEMM output (h * dinv[row])
__device__ float g_agg[NNODES * CDIM];   // scatter accumulator
__device__ float g_h1 [NNODES * CDIM];   // layer-1 activation (input to GEMM2)

// ---------------------------------------------------------------------------
__global__ void zero_int_k(int* __restrict__ p, int n) {
    int i = blockIdx.x * blockDim.x + threadIdx.x;
    if (i < n) p[i] = 0;
}

__global__ void zero_f4_k(float4* __restrict__ p, int n4) {
    int i = blockIdx.x * blockDim.x + threadIdx.x;
    if (i < n4) p[i] = make_float4(0.f, 0.f, 0.f, 0.f);
}

__global__ void degree_k(const int* __restrict__ dst, int E) {
    int i = blockIdx.x * blockDim.x + threadIdx.x;
    if (i < E) atomicAdd(&g_deg[dst[i]], 1);
}

__global__ void dinv_k(int n) {
    int i = blockIdx.x * blockDim.x + threadIdx.x;
    if (i < n) g_dinv[i] = rsqrtf((float)g_deg[i] + 1.0f);  // +1 = self loop
}

// ---------------------------------------------------------------------------
// C[M,256] = (A[M,K] @ B[K,256]) * dinv[row]   (row-scaled epilogue)
// 128x128 block tile, BK=8, 256 threads, 8x8 per-thread micro-tile.
__global__ __launch_bounds__(256) void sgemm_dinv_k(
    const float* __restrict__ A, const float* __restrict__ B,
    float* __restrict__ C, int M, int K)
{
    const int N = CDIM;
    __shared__ float As[8][128];
    __shared__ float Bs[8][128];

    int tid  = threadIdx.x;
    int row0 = blockIdx.y * 128;
    int col0 = blockIdx.x * 128;

    int a_r = tid >> 1;           // 0..127
    int a_c = (tid & 1) * 4;      // 0 or 4
    int b_r = tid >> 5;           // 0..7
    int b_c = (tid & 31) * 4;     // 0..124

    int ty = tid >> 4;            // 0..15 -> rows ty*8..ty*8+7
    int tx = tid & 15;            // 0..15 -> cols tx*8..tx*8+7

    float acc[8][8];
    #pragma unroll
    for (int i = 0; i < 8; i++)
        #pragma unroll
        for (int j = 0; j < 8; j++) acc[i][j] = 0.f;

    for (int k0 = 0; k0 < K; k0 += 8) {
        float4 av = make_float4(0.f, 0.f, 0.f, 0.f);
        int gr = row0 + a_r;
        if (gr < M)
            av = *reinterpret_cast<const float4*>(A + (size_t)gr * K + k0 + a_c);
        As[a_c + 0][a_r] = av.x;
        As[a_c + 1][a_r] = av.y;
        As[a_c + 2][a_r] = av.z;
        As[a_c + 3][a_r] = av.w;

        float4 bv = *reinterpret_cast<const float4*>(
            B + (size_t)(k0 + b_r) * N + col0 + b_c);
        *reinterpret_cast<float4*>(&Bs[b_r][b_c]) = bv;

        __syncthreads();

        #pragma unroll
        for (int kk = 0; kk < 8; kk++) {
            float ra[8], rb[8];
            #pragma unroll
            for (int i = 0; i < 8; i++) ra[i] = As[kk][ty * 8 + i];
            #pragma unroll
            for (int j = 0; j < 8; j++) rb[j] = Bs[kk][tx * 8 + j];
            #pragma unroll
            for (int i = 0; i < 8; i++)
                #pragma unroll
                for (int j = 0; j < 8; j++)
                    acc[i][j] = fmaf(ra[i], rb[j], acc[i][j]);
        }
        __syncthreads();
    }

    #pragma unroll
    for (int i = 0; i < 8; i++) {
        int gr = row0 + ty * 8 + i;
        if (gr < M) {
            float s = g_dinv[gr];
            float4 o0 = make_float4(acc[i][0] * s, acc[i][1] * s,
                                    acc[i][2] * s, acc[i][3] * s);
            float4 o1 = make_float4(acc[i][4] * s, acc[i][5] * s,
                                    acc[i][6] * s, acc[i][7] * s);
            float* cp = C + (size_t)gr * N + col0 + tx * 8;
            *reinterpret_cast<float4*>(cp)     = o0;
            *reinterpret_cast<float4*>(cp + 4) = o1;
        }
    }
}

// ---------------------------------------------------------------------------
// Per edge: agg[dst] += hs[src]  (64 threads/edge, float4 lanes, vector red)
__global__ void scatter_k(const int* __restrict__ src,
                          const int* __restrict__ dst, int E)
{
    int e = blockIdx.x * 4 + (threadIdx.x >> 6);
    if (e >= E) return;
    int lane = threadIdx.x & 63;
    int s = src[e];
    int d = dst[e];
    const float4 v = *reinterpret_cast<const float4*>(
        g_hs + (size_t)s * CDIM + lane * 4);
    float* p = g_agg + (size_t)d * CDIM + lane * 4;
    asm volatile("red.global.add.v4.f32 [%0], {%1, %2, %3, %4};"
                 :: "l"(p), "f"(v.x), "f"(v.y), "f"(v.z), "f"(v.w)
                 : "memory");
}

// ---------------------------------------------------------------------------
// out[i,c] = act( (agg[i,c] + hs[i,c]) * dinv[i] + b[c] )
// (agg holds sum of scaled neighbor rows; + hs[i] is the self loop; * dinv[i]
//  applies the dst-side normalization factor)
__global__ void finalize_k(const float* __restrict__ b,
                           float* __restrict__ out, int relu)
{
    int i = blockIdx.x * blockDim.x + threadIdx.x;   // over NNODES*64 float4s
    if (i >= NNODES * (CDIM / 4)) return;
    int row = i >> 6;
    int c4  = (i & 63) * 4;
    float s = g_dinv[row];
    const float4 a  = *reinterpret_cast<const float4*>(g_agg + (size_t)row * CDIM + c4);
    const float4 h  = *reinterpret_cast<const float4*>(g_hs  + (size_t)row * CDIM + c4);
    const float4 bb = *reinterpret_cast<const float4*>(b + c4);
    float4 o;
    o.x = fmaf(a.x + h.x, s, bb.x);
    o.y = fmaf(a.y + h.y, s, bb.y);
    o.z = fmaf(a.z + h.z, s, bb.z);
    o.w = fmaf(a.w + h.w, s, bb.w);
    if (relu) {
        o.x = fmaxf(o.x, 0.f); o.y = fmaxf(o.y, 0.f);
        o.z = fmaxf(o.z, 0.f); o.w = fmaxf(o.w, 0.f);
    }
    *reinterpret_cast<float4*>(out + (size_t)row * CDIM + c4) = o;
}

// ---------------------------------------------------------------------------
extern "C" void kernel_launch(void* const* d_in, const int* in_sizes, int n_in,
                              void* d_out, int out_size)
{
    const float* x  = (const float*)d_in[0];   // [50000, 768]
    const int*   ei = (const int*)  d_in[1];   // [2, 800000]
    const float* W1 = (const float*)d_in[2];   // [768, 256]
    const float* b1 = (const float*)d_in[3];   // [256]
    const float* W2 = (const float*)d_in[4];   // [256, 256]
    const float* b2 = (const float*)d_in[5];   // [256]
    (void)in_sizes; (void)n_in; (void)out_size;

    const int* src = ei;
    const int* dst = ei + NEDGES;

    float *hs, *agg, *h1;
    int* degp;
    cudaGetSymbolAddress((void**)&hs,  g_hs);
    cudaGetSymbolAddress((void**)&agg, g_agg);
    cudaGetSymbolAddress((void**)&h1,  g_h1);
    cudaGetSymbolAddress((void**)&degp, g_deg);

    const int n4 = NNODES * (CDIM / 4);            // 3.2M float4
    const dim3 gemm_grid(CDIM / 128, (NNODES + 127) / 128);  // (2, 391)

    // degrees + dinv
    zero_int_k<<<(NNODES + 255) / 256, 256>>>(degp, NNODES);
    degree_k  <<<(NEDGES + 255) / 256, 256>>>(dst, NEDGES);
    dinv_k    <<<(NNODES + 255) / 256, 256>>>(NNODES);

    // layer 1
    sgemm_dinv_k<<<gemm_grid, 256>>>(x, W1, hs, NNODES, FIN);
    zero_f4_k   <<<(n4 + 255) / 256, 256>>>((float4*)agg, n4);
    scatter_k   <<<(NEDGES + 3) / 4, 256>>>(src, dst, NEDGES);
    finalize_k  <<<(n4 + 255) / 256, 256>>>(b1, h1, 1);

    // layer 2
    sgemm_dinv_k<<<gemm_grid, 256>>>(h1, W2, hs, NNODES, CDIM);
    zero_f4_k   <<<(n4 + 255) / 256, 256>>>((float4*)agg, n4);
    scatter_k   <<<(NEDGES + 3) / 4, 256>>>(src, dst, NEDGES);
    finalize_k  <<<(n4 + 255) / 256, 256>>>(b2, (float*)d_out, 0);
}

// round 4
// speedup vs baseline: 1.6358x; 1.6358x over previous
#include <cuda_runtime.h>
#include <cstdint>

#define NNODES 50000
#define NEDGES 800000
#define CDIM 256
#define FIN 768

#define BM 128
#define BN 128
#define KCH 16
#define PITCH 20   // floats; 20*g mod 32 spans all banks -> conflict-free frags

// Scratch (allocation-free rule: device globals)
__device__ float g_dinv[NNODES];
__device__ int   g_deg[NNODES];
__device__ float g_hs [NNODES * CDIM];   // row-scaled GEMM output (h * dinv[row])
__device__ float g_agg[NNODES * CDIM];   // scatter accumulator
__device__ float g_h1 [NNODES * CDIM];   // layer-1 activation
__device__ float g_WT1[CDIM * FIN];      // W1^T, tf32-rounded, [N=256, K=768]
__device__ float g_WT2[CDIM * CDIM];     // W2^T, tf32-rounded, [N=256, K=256]

__device__ __forceinline__ uint32_t f2tf32(float f) {
    uint32_t u;
    asm("cvt.rna.tf32.f32 %0, %1;" : "=r"(u) : "f"(f));
    return u;
}

__device__ __forceinline__ void mma_tf32(float* c, const uint32_t* a, const uint32_t* b) {
    asm volatile(
        "mma.sync.aligned.m16n8k8.row.col.f32.tf32.tf32.f32 "
        "{%0,%1,%2,%3}, {%4,%5,%6,%7}, {%8,%9}, {%0,%1,%2,%3};"
        : "+f"(c[0]), "+f"(c[1]), "+f"(c[2]), "+f"(c[3])
        : "r"(a[0]), "r"(a[1]), "r"(a[2]), "r"(a[3]), "r"(b[0]), "r"(b[1]));
}

// ---------------------------------------------------------------------------
__global__ void zero_int_k(int* __restrict__ p, int n) {
    int i = blockIdx.x * blockDim.x + threadIdx.x;
    if (i < n) p[i] = 0;
}
__global__ void zero_f4_k(float4* __restrict__ p, int n4) {
    int i = blockIdx.x * blockDim.x + threadIdx.x;
    if (i < n4) p[i] = make_float4(0.f, 0.f, 0.f, 0.f);
}
__global__ void degree_k(const int* __restrict__ dst, int E) {
    int i = blockIdx.x * blockDim.x + threadIdx.x;
    if (i < E) atomicAdd(&g_deg[dst[i]], 1);
}
__global__ void dinv_k(int n) {
    int i = blockIdx.x * blockDim.x + threadIdx.x;
    if (i < n) g_dinv[i] = rsqrtf((float)g_deg[i] + 1.0f);  // +1 = self loop
}

// WT[n][k] = tf32(W[k][n]);  W is [K, 256] row-major
__global__ void transpose_tf32_k(const float* __restrict__ W,
                                 float* __restrict__ WT, int K) {
    int idx = blockIdx.x * blockDim.x + threadIdx.x;
    if (idx >= K * CDIM) return;
    int n = idx & (CDIM - 1);
    int k = idx >> 8;
    WT[(size_t)n * K + k] = __uint_as_float(f2tf32(W[(size_t)k * CDIM + n]));
}

// ---------------------------------------------------------------------------
// C[M,256] = (A[M,K] @ WT^T) * dinv[row]  — mma.sync tf32, 128x128 CTA tile
// ---------------------------------------------------------------------------
__global__ __launch_bounds__(256, 2) void gemm_mma_k(
    const float* __restrict__ A, const float* __restrict__ WT,
    float* __restrict__ C, int M, int K)
{
    __shared__ float As[2][BM * PITCH];
    __shared__ float Bs[2][BN * PITCH];

    const int tid  = threadIdx.x;
    const int lane = tid & 31;
    const int wid  = tid >> 5;
    const int wm   = wid & 1;          // 0..1  (64-row warp tiles)
    const int wn   = wid >> 1;         // 0..3  (32-col warp tiles)
    const int gq   = lane >> 2;        // group id 0..7
    const int cq   = lane & 3;         // thread-in-group 0..3
    const int row0 = blockIdx.y * BM;
    const int col0 = blockIdx.x * BN;

    const int lr = tid >> 2;           // 0..63  (row within tile, +t*64)
    const int kq = (tid & 3) * 4;      // k offset within chunk (float4)

    float acc[4][4][4];
    #pragma unroll
    for (int mt = 0; mt < 4; mt++)
        #pragma unroll
        for (int nt = 0; nt < 4; nt++)
            #pragma unroll
            for (int q = 0; q < 4; q++) acc[mt][nt][q] = 0.f;

    const int nkc = K / KCH;
    float4 pa[2], pb[2];

    auto load_chunk = [&](int kc) {
        #pragma unroll
        for (int t = 0; t < 2; t++) {
            int r  = lr + t * 64;
            int gr = row0 + r;
            float4 v = make_float4(0.f, 0.f, 0.f, 0.f);
            if (gr < M)
                v = *reinterpret_cast<const float4*>(A + (size_t)gr * K + kc * KCH + kq);
            pa[t] = v;
            pb[t] = *reinterpret_cast<const float4*>(
                WT + (size_t)(col0 + r) * K + kc * KCH + kq);
        }
    };
    auto store_chunk = [&](int buf) {
        #pragma unroll
        for (int t = 0; t < 2; t++) {
            int r = lr + t * 64;
            uint4 u;
            u.x = f2tf32(pa[t].x); u.y = f2tf32(pa[t].y);
            u.z = f2tf32(pa[t].z); u.w = f2tf32(pa[t].w);
            *reinterpret_cast<uint4*>(&As[buf][r * PITCH + kq]) = u;
            *reinterpret_cast<float4*>(&Bs[buf][r * PITCH + kq]) = pb[t];
        }
    };

    load_chunk(0);
    store_chunk(0);
    __syncthreads();

    for (int kc = 0; kc < nkc; kc++) {
        const int cur = kc & 1;
        const bool more = (kc + 1) < nkc;
        if (more) load_chunk(kc + 1);

        #pragma unroll
        for (int k0 = 0; k0 < KCH; k0 += 8) {
            uint32_t bf[4][2];
            #pragma unroll
            for (int nt = 0; nt < 4; nt++) {
                int n = wn * 32 + nt * 8 + gq;
                bf[nt][0] = __float_as_uint(Bs[cur][n * PITCH + k0 + cq]);
                bf[nt][1] = __float_as_uint(Bs[cur][n * PITCH + k0 + cq + 4]);
            }
            #pragma unroll
            for (int mt = 0; mt < 4; mt++) {
                int r = wm * 64 + mt * 16 + gq;
                uint32_t af[4];
                af[0] = __float_as_uint(As[cur][(r    ) * PITCH + k0 + cq    ]);
                af[1] = __float_as_uint(As[cur][(r + 8) * PITCH + k0 + cq    ]);
                af[2] = __float_as_uint(As[cur][(r    ) * PITCH + k0 + cq + 4]);
                af[3] = __float_as_uint(As[cur][(r + 8) * PITCH + k0 + cq + 4]);
                #pragma unroll
                for (int nt = 0; nt < 4; nt++)
                    mma_tf32(acc[mt][nt], af, bf[nt]);
            }
        }
        __syncthreads();
        if (more) {
            store_chunk(cur ^ 1);
            __syncthreads();
        }
    }

    // epilogue: scale by dinv[row], store fp32 as float2 (c0,c1 adjacent cols)
    #pragma unroll
    for (int mt = 0; mt < 4; mt++) {
        #pragma unroll
        for (int h = 0; h < 2; h++) {
            int row = row0 + wm * 64 + mt * 16 + gq + h * 8;
            if (row < M) {
                float s = g_dinv[row];
                float* cp = C + (size_t)row * CDIM + col0 + wn * 32;
                #pragma unroll
                for (int nt = 0; nt < 4; nt++) {
                    float2 o;
                    o.x = acc[mt][nt][h * 2 + 0] * s;
                    o.y = acc[mt][nt][h * 2 + 1] * s;
                    *reinterpret_cast<float2*>(cp + nt * 8 + cq * 2) = o;
                }
            }
        }
    }
}

// ---------------------------------------------------------------------------
// Per edge: agg[dst] += hs[src]  (64 threads/edge, float4 lanes, vector red)
__global__ void scatter_k(const int* __restrict__ src,
                          const int* __restrict__ dst, int E)
{
    int e = blockIdx.x * 4 + (threadIdx.x >> 6);
    if (e >= E) return;
    int lane = threadIdx.x & 63;
    int s = src[e];
    int d = dst[e];
    const float4 v = *reinterpret_cast<const float4*>(
        g_hs + (size_t)s * CDIM + lane * 4);
    float* p = g_agg + (size_t)d * CDIM + lane * 4;
    asm volatile("red.global.add.v4.f32 [%0], {%1, %2, %3, %4};"
                 :: "l"(p), "f"(v.x), "f"(v.y), "f"(v.z), "f"(v.w)
                 : "memory");
}

// out[i,c] = act( (agg[i,c] + hs[i,c]) * dinv[i] + b[c] )
__global__ void finalize_k(const float* __restrict__ b,
                           float* __restrict__ out, int relu)
{
    int i = blockIdx.x * blockDim.x + threadIdx.x;
    if (i >= NNODES * (CDIM / 4)) return;
    int row = i >> 6;
    int c4  = (i & 63) * 4;
    float s = g_dinv[row];
    const float4 a  = *reinterpret_cast<const float4*>(g_agg + (size_t)row * CDIM + c4);
    const float4 h  = *reinterpret_cast<const float4*>(g_hs  + (size_t)row * CDIM + c4);
    const float4 bb = *reinterpret_cast<const float4*>(b + c4);
    float4 o;
    o.x = fmaf(a.x + h.x, s, bb.x);
    o.y = fmaf(a.y + h.y, s, bb.y);
    o.z = fmaf(a.z + h.z, s, bb.z);
    o.w = fmaf(a.w + h.w, s, bb.w);
    if (relu) {
        o.x = fmaxf(o.x, 0.f); o.y = fmaxf(o.y, 0.f);
        o.z = fmaxf(o.z, 0.f); o.w = fmaxf(o.w, 0.f);
    }
    *reinterpret_cast<float4*>(out + (size_t)row * CDIM + c4) = o;
}

// ---------------------------------------------------------------------------
extern "C" void kernel_launch(void* const* d_in, const int* in_sizes, int n_in,
                              void* d_out, int out_size)
{
    const float* x  = (const float*)d_in[0];
    const int*   ei = (const int*)  d_in[1];
    const float* W1 = (const float*)d_in[2];
    const float* b1 = (const float*)d_in[3];
    const float* W2 = (const float*)d_in[4];
    const float* b2 = (const float*)d_in[5];
    (void)in_sizes; (void)n_in; (void)out_size;

    const int* src = ei;
    const int* dst = ei + NEDGES;

    float *hs, *agg, *h1, *wt1, *wt2;
    int* degp;
    cudaGetSymbolAddress((void**)&hs,  g_hs);
    cudaGetSymbolAddress((void**)&agg, g_agg);
    cudaGetSymbolAddress((void**)&h1,  g_h1);
    cudaGetSymbolAddress((void**)&wt1, g_WT1);
    cudaGetSymbolAddress((void**)&wt2, g_WT2);
    cudaGetSymbolAddress((void**)&degp, g_deg);

    const int n4 = NNODES * (CDIM / 4);
    const dim3 gemm_grid(CDIM / BN, (NNODES + BM - 1) / BM);   // (2, 391)

    // weight transposes (tf32 rounding) + degrees
    transpose_tf32_k<<<(FIN * CDIM + 255) / 256, 256>>>(W1, wt1, FIN);
    transpose_tf32_k<<<(CDIM * CDIM + 255) / 256, 256>>>(W2, wt2, CDIM);
    zero_int_k<<<(NNODES + 255) / 256, 256>>>(degp, NNODES);
    degree_k  <<<(NEDGES + 255) / 256, 256>>>(dst, NEDGES);
    dinv_k    <<<(NNODES + 255) / 256, 256>>>(NNODES);

    // layer 1
    gemm_mma_k<<<gemm_grid, 256>>>(x, wt1, hs, NNODES, FIN);
    zero_f4_k <<<(n4 + 255) / 256, 256>>>((float4*)agg, n4);
    scatter_k <<<(NEDGES + 3) / 4, 256>>>(src, dst, NEDGES);
    finalize_k<<<(n4 + 255) / 256, 256>>>(b1, h1, 1);

    // layer 2
    gemm_mma_k<<<gemm_grid, 256>>>(h1, wt2, hs, NNODES, CDIM);
    zero_f4_k <<<(n4 + 255) / 256, 256>>>((float4*)agg, n4);
    scatter_k <<<(NEDGES + 3) / 4, 256>>>(src, dst, NEDGES);
    finalize_k<<<(n4 + 255) / 256, 256>>>(b2, (float*)d_out, 0);
}

// round 5
// speedup vs baseline: 2.3983x; 1.4661x over previous
#include <cuda_runtime.h>
#include <cstdint>

#define NNODES 50000
#define NEDGES 800000
#define CDIM 256
#define FIN 768

#define BM 128
#define BN 128
#define KCH 16
#define PITCH 20   // floats; 20*g mod 32 spans all banks -> conflict-free frags

// Scratch (allocation-free rule: device globals)
__device__ float g_dinv[NNODES];
__device__ int   g_deg[NNODES];
__device__ int   g_off[NNODES + 1];
__device__ int   g_cur[NNODES];
__device__ int   g_csrc[NEDGES];         // edge sources, grouped by dst
__device__ float g_hs [NNODES * CDIM];   // row-scaled GEMM output (h * dinv[row])
__device__ float g_h1 [NNODES * CDIM];   // layer-1 activation
__device__ float g_WT1[CDIM * FIN];      // W1^T, tf32-rounded
__device__ float g_WT2[CDIM * CDIM];     // W2^T, tf32-rounded

__device__ __forceinline__ uint32_t f2tf32(float f) {
    uint32_t u;
    asm("cvt.rna.tf32.f32 %0, %1;" : "=r"(u) : "f"(f));
    return u;
}

__device__ __forceinline__ void mma_tf32(float* c, const uint32_t* a, const uint32_t* b) {
    asm volatile(
        "mma.sync.aligned.m16n8k8.row.col.f32.tf32.tf32.f32 "
        "{%0,%1,%2,%3}, {%4,%5,%6,%7}, {%8,%9}, {%0,%1,%2,%3};"
        : "+f"(c[0]), "+f"(c[1]), "+f"(c[2]), "+f"(c[3])
        : "r"(a[0]), "r"(a[1]), "r"(a[2]), "r"(a[3]), "r"(b[0]), "r"(b[1]));
}

// ---------------------------------------------------------------------------
__global__ void zero_int_k(int* __restrict__ p, int n) {
    int i = blockIdx.x * blockDim.x + threadIdx.x;
    if (i < n) p[i] = 0;
}
__global__ void degree_k(const int* __restrict__ dst, int E) {
    int i = blockIdx.x * blockDim.x + threadIdx.x;
    if (i < E) atomicAdd(&g_deg[dst[i]], 1);
}
__global__ void dinv_k(int n) {
    int i = blockIdx.x * blockDim.x + threadIdx.x;
    if (i < n) g_dinv[i] = rsqrtf((float)g_deg[i] + 1.0f);  // +1 = self loop
}

// Single-block exclusive scan of degrees -> g_off / g_cur (1024 threads)
__global__ void scan_k() {
    __shared__ int sums[1024];
    const int T = 1024;
    const int chunk = (NNODES + T - 1) / T;   // 49
    int t = threadIdx.x;
    int base = t * chunk;
    int s = 0;
    for (int j = 0; j < chunk; j++) {
        int i = base + j;
        if (i < NNODES) s += g_deg[i];
    }
    sums[t] = s;
    __syncthreads();
    for (int d = 1; d < T; d <<= 1) {
        int v = (t >= d) ? sums[t - d] : 0;
        __syncthreads();
        sums[t] += v;
        __syncthreads();
    }
    int run = (t == 0) ? 0 : sums[t - 1];
    for (int j = 0; j < chunk; j++) {
        int i = base + j;
        if (i < NNODES) {
            g_off[i] = run;
            g_cur[i] = run;
            run += g_deg[i];
        }
    }
    if (t == T - 1) g_off[NNODES] = run;
}

__global__ void csr_fill_k(const int* __restrict__ src,
                           const int* __restrict__ dst, int E) {
    int e = blockIdx.x * blockDim.x + threadIdx.x;
    if (e < E) {
        int p = atomicAdd(&g_cur[dst[e]], 1);
        g_csrc[p] = src[e];
    }
}

// WT[n][k] = tf32(W[k][n]);  W is [K, 256] row-major
__global__ void transpose_tf32_k(const float* __restrict__ W,
                                 float* __restrict__ WT, int K) {
    int idx = blockIdx.x * blockDim.x + threadIdx.x;
    if (idx >= K * CDIM) return;
    int n = idx & (CDIM - 1);
    int k = idx >> 8;
    WT[(size_t)n * K + k] = __uint_as_float(f2tf32(W[(size_t)k * CDIM + n]));
}

// ---------------------------------------------------------------------------
// C[M,256] = (A[M,K] @ WT^T) * dinv[row]  — mma.sync tf32, 128x128 CTA tile
// ---------------------------------------------------------------------------
__global__ __launch_bounds__(256, 2) void gemm_mma_k(
    const float* __restrict__ A, const float* __restrict__ WT,
    float* __restrict__ C, int M, int K)
{
    __shared__ float As[2][BM * PITCH];
    __shared__ float Bs[2][BN * PITCH];

    const int tid  = threadIdx.x;
    const int lane = tid & 31;
    const int wid  = tid >> 5;
    const int wm   = wid & 1;
    const int wn   = wid >> 1;
    const int gq   = lane >> 2;
    const int cq   = lane & 3;
    const int row0 = blockIdx.y * BM;
    const int col0 = blockIdx.x * BN;

    const int lr = tid >> 2;
    const int kq = (tid & 3) * 4;

    float acc[4][4][4];
    #pragma unroll
    for (int mt = 0; mt < 4; mt++)
        #pragma unroll
        for (int nt = 0; nt < 4; nt++)
            #pragma unroll
            for (int q = 0; q < 4; q++) acc[mt][nt][q] = 0.f;

    const int nkc = K / KCH;
    float4 pa[2], pb[2];

    auto load_chunk = [&](int kc) {
        #pragma unroll
        for (int t = 0; t < 2; t++) {
            int r  = lr + t * 64;
            int gr = row0 + r;
            float4 v = make_float4(0.f, 0.f, 0.f, 0.f);
            if (gr < M)
                v = *reinterpret_cast<const float4*>(A + (size_t)gr * K + kc * KCH + kq);
            pa[t] = v;
            pb[t] = *reinterpret_cast<const float4*>(
                WT + (size_t)(col0 + r) * K + kc * KCH + kq);
        }
    };
    auto store_chunk = [&](int buf) {
        #pragma unroll
        for (int t = 0; t < 2; t++) {
            int r = lr + t * 64;
            uint4 u;
            u.x = f2tf32(pa[t].x); u.y = f2tf32(pa[t].y);
            u.z = f2tf32(pa[t].z); u.w = f2tf32(pa[t].w);
            *reinterpret_cast<uint4*>(&As[buf][r * PITCH + kq]) = u;
            *reinterpret_cast<float4*>(&Bs[buf][r * PITCH + kq]) = pb[t];
        }
    };

    load_chunk(0);
    store_chunk(0);
    __syncthreads();

    for (int kc = 0; kc < nkc; kc++) {
        const int cur = kc & 1;
        const bool more = (kc + 1) < nkc;
        if (more) load_chunk(kc + 1);

        #pragma unroll
        for (int k0 = 0; k0 < KCH; k0 += 8) {
            uint32_t bf[4][2];
            #pragma unroll
            for (int nt = 0; nt < 4; nt++) {
                int n = wn * 32 + nt * 8 + gq;
                bf[nt][0] = __float_as_uint(Bs[cur][n * PITCH + k0 + cq]);
                bf[nt][1] = __float_as_uint(Bs[cur][n * PITCH + k0 + cq + 4]);
            }
            #pragma unroll
            for (int mt = 0; mt < 4; mt++) {
                int r = wm * 64 + mt * 16 + gq;
                uint32_t af[4];
                af[0] = __float_as_uint(As[cur][(r    ) * PITCH + k0 + cq    ]);
                af[1] = __float_as_uint(As[cur][(r + 8) * PITCH + k0 + cq    ]);
                af[2] = __float_as_uint(As[cur][(r    ) * PITCH + k0 + cq + 4]);
                af[3] = __float_as_uint(As[cur][(r + 8) * PITCH + k0 + cq + 4]);
                #pragma unroll
                for (int nt = 0; nt < 4; nt++)
                    mma_tf32(acc[mt][nt], af, bf[nt]);
            }
        }
        __syncthreads();
        if (more) {
            store_chunk(cur ^ 1);
            __syncthreads();
        }
    }

    #pragma unroll
    for (int mt = 0; mt < 4; mt++) {
        #pragma unroll
        for (int h = 0; h < 2; h++) {
            int row = row0 + wm * 64 + mt * 16 + gq + h * 8;
            if (row < M) {
                float s = g_dinv[row];
                float* cp = C + (size_t)row * CDIM + col0 + wn * 32;
                #pragma unroll
                for (int nt = 0; nt < 4; nt++) {
                    float2 o;
                    o.x = acc[mt][nt][h * 2 + 0] * s;
                    o.y = acc[mt][nt][h * 2 + 1] * s;
                    *reinterpret_cast<float2*>(cp + nt * 8 + cq * 2) = o;
                }
            }
        }
    }
}

// ---------------------------------------------------------------------------
// Fused CSR gather + self-loop + dinv[dst] + bias (+relu): 64 threads/node.
// out[i] = act( (sum_{s in N(i)} hs[s] + hs[i]) * dinv[i] + b )
// ---------------------------------------------------------------------------
__global__ __launch_bounds__(256) void agg_k(const float* __restrict__ b,
                                             float* __restrict__ out, int relu)
{
    int node = blockIdx.x * 4 + (threadIdx.x >> 6);
    if (node >= NNODES) return;
    int lane = threadIdx.x & 63;

    const float4* hs4 = reinterpret_cast<const float4*>(g_hs);
    float4 acc = hs4[(size_t)node * 64 + lane];   // self loop (already *dinv[i])

    int j   = g_off[node];
    int end = g_off[node + 1];
    for (; j + 1 < end; j += 2) {
        int s0 = g_csrc[j];
        int s1 = g_csrc[j + 1];
        float4 v0 = hs4[(size_t)s0 * 64 + lane];
        float4 v1 = hs4[(size_t)s1 * 64 + lane];
        acc.x += v0.x; acc.y += v0.y; acc.z += v0.z; acc.w += v0.w;
        acc.x += v1.x; acc.y += v1.y; acc.z += v1.z; acc.w += v1.w;
    }
    if (j < end) {
        int s0 = g_csrc[j];
        float4 v0 = hs4[(size_t)s0 * 64 + lane];
        acc.x += v0.x; acc.y += v0.y; acc.z += v0.z; acc.w += v0.w;
    }

    float s = g_dinv[node];
    const float4 bb = *reinterpret_cast<const float4*>(b + lane * 4);
    float4 o;
    o.x = fmaf(acc.x, s, bb.x);
    o.y = fmaf(acc.y, s, bb.y);
    o.z = fmaf(acc.z, s, bb.z);
    o.w = fmaf(acc.w, s, bb.w);
    if (relu) {
        o.x = fmaxf(o.x, 0.f); o.y = fmaxf(o.y, 0.f);
        o.z = fmaxf(o.z, 0.f); o.w = fmaxf(o.w, 0.f);
    }
    reinterpret_cast<float4*>(out)[(size_t)node * 64 + lane] = o;
}

// ---------------------------------------------------------------------------
extern "C" void kernel_launch(void* const* d_in, const int* in_sizes, int n_in,
                              void* d_out, int out_size)
{
    const float* x  = (const float*)d_in[0];
    const int*   ei = (const int*)  d_in[1];
    const float* W1 = (const float*)d_in[2];
    const float* b1 = (const float*)d_in[3];
    const float* W2 = (const float*)d_in[4];
    const float* b2 = (const float*)d_in[5];
    (void)in_sizes; (void)n_in; (void)out_size;

    const int* src = ei;
    const int* dst = ei + NEDGES;

    float *hs, *h1, *wt1, *wt2;
    int* degp;
    cudaGetSymbolAddress((void**)&hs,  g_hs);
    cudaGetSymbolAddress((void**)&h1,  g_h1);
    cudaGetSymbolAddress((void**)&wt1, g_WT1);
    cudaGetSymbolAddress((void**)&wt2, g_WT2);
    cudaGetSymbolAddress((void**)&degp, g_deg);

    const dim3 gemm_grid(CDIM / BN, (NNODES + BM - 1) / BM);   // (2, 391)
    const int agg_grid = (NNODES + 3) / 4;                     // 12500

    // weight transposes (tf32 rounding) + CSR build
    transpose_tf32_k<<<(FIN * CDIM + 255) / 256, 256>>>(W1, wt1, FIN);
    transpose_tf32_k<<<(CDIM * CDIM + 255) / 256, 256>>>(W2, wt2, CDIM);
    zero_int_k<<<(NNODES + 255) / 256, 256>>>(degp, NNODES);
    degree_k  <<<(NEDGES + 255) / 256, 256>>>(dst, NEDGES);
    dinv_k    <<<(NNODES + 255) / 256, 256>>>(NNODES);
    scan_k    <<<1, 1024>>>();
    csr_fill_k<<<(NEDGES + 255) / 256, 256>>>(src, dst, NEDGES);

    // layer 1
    gemm_mma_k<<<gemm_grid, 256>>>(x, wt1, hs, NNODES, FIN);
    agg_k     <<<agg_grid, 256>>>(b1, h1, 1);

    // layer 2
    gemm_mma_k<<<gemm_grid, 256>>>(h1, wt2, hs, NNODES, CDIM);
    agg_k     <<<agg_grid, 256>>>(b2, (float*)d_out, 0);
}

// round 6
// speedup vs baseline: 2.6072x; 1.0871x over previous
#include <cuda_runtime.h>
#include <cstdint>

#define NNODES 50000
#define NEDGES 800000
#define CDIM 256
#define FIN 768

#define BM 128
#define BN 128
#define KCH 16
#define PITCH 20   // floats; conflict-free fragment loads
#define BUFB (BM * PITCH * 4)   // bytes per buffer stage

// Scratch (allocation-free rule: device globals)
__device__ float g_dinv[NNODES];
__device__ int   g_deg[NNODES];
__device__ int   g_off[NNODES + 1];
__device__ int   g_cur[NNODES];
__device__ int   g_csrc[NEDGES];         // edge sources, grouped by dst
__device__ float g_hs [NNODES * CDIM];   // row-scaled GEMM output (h * dinv[row])
__device__ float g_h1 [NNODES * CDIM];   // layer-1 activation
__device__ float g_WT1[CDIM * FIN];      // W1^T, tf32-rounded
__device__ float g_WT2[CDIM * CDIM];     // W2^T, tf32-rounded

__device__ __forceinline__ uint32_t smem_u32(const void* p) {
    uint32_t a;
    asm("{ .reg .u64 t; cvta.to.shared.u64 t, %1; cvt.u32.u64 %0, t; }"
        : "=r"(a) : "l"(p));
    return a;
}
__device__ __forceinline__ uint32_t f2tf32(float f) {
    uint32_t u;
    asm("cvt.rna.tf32.f32 %0, %1;" : "=r"(u) : "f"(f));
    return u;
}
__device__ __forceinline__ void mma_tf32(float* c, const uint32_t* a, const uint32_t* b) {
    asm volatile(
        "mma.sync.aligned.m16n8k8.row.col.f32.tf32.tf32.f32 "
        "{%0,%1,%2,%3}, {%4,%5,%6,%7}, {%8,%9}, {%0,%1,%2,%3};"
        : "+f"(c[0]), "+f"(c[1]), "+f"(c[2]), "+f"(c[3])
        : "r"(a[0]), "r"(a[1]), "r"(a[2]), "r"(a[3]), "r"(b[0]), "r"(b[1]));
}

// ---------------------------------------------------------------------------
__global__ void zero_int_k(int* __restrict__ p, int n) {
    int i = blockIdx.x * blockDim.x + threadIdx.x;
    if (i < n) p[i] = 0;
}
__global__ void degree_k(const int* __restrict__ dst, int E4) {
    int i = blockIdx.x * blockDim.x + threadIdx.x;
    if (i < E4) {
        int4 d = reinterpret_cast<const int4*>(dst)[i];
        atomicAdd(&g_deg[d.x], 1);
        atomicAdd(&g_deg[d.y], 1);
        atomicAdd(&g_deg[d.z], 1);
        atomicAdd(&g_deg[d.w], 1);
    }
}
__global__ void dinv_k(int n) {
    int i = blockIdx.x * blockDim.x + threadIdx.x;
    if (i < n) g_dinv[i] = rsqrtf((float)g_deg[i] + 1.0f);  // +1 = self loop
}

// Single-block exclusive scan of degrees -> g_off / g_cur (1024 threads)
__global__ void scan_k() {
    __shared__ int sums[1024];
    const int T = 1024;
    const int chunk = (NNODES + T - 1) / T;
    int t = threadIdx.x;
    int base = t * chunk;
    int s = 0;
    for (int j = 0; j < chunk; j++) {
        int i = base + j;
        if (i < NNODES) s += g_deg[i];
    }
    sums[t] = s;
    __syncthreads();
    for (int d = 1; d < T; d <<= 1) {
        int v = (t >= d) ? sums[t - d] : 0;
        __syncthreads();
        sums[t] += v;
        __syncthreads();
    }
    int run = (t == 0) ? 0 : sums[t - 1];
    for (int j = 0; j < chunk; j++) {
        int i = base + j;
        if (i < NNODES) {
            g_off[i] = run;
            g_cur[i] = run;
            run += g_deg[i];
        }
    }
    if (t == T - 1) g_off[NNODES] = run;
}

__global__ void csr_fill_k(const int* __restrict__ src,
                           const int* __restrict__ dst, int E) {
    int e = blockIdx.x * blockDim.x + threadIdx.x;
    if (e < E) {
        int p = atomicAdd(&g_cur[dst[e]], 1);
        g_csrc[p] = src[e];
    }
}

// WT[n][k] = tf32(W[k][n]);  W is [K, 256] row-major
__global__ void transpose_tf32_k(const float* __restrict__ W,
                                 float* __restrict__ WT, int K) {
    int idx = blockIdx.x * blockDim.x + threadIdx.x;
    if (idx >= K * CDIM) return;
    int n = idx & (CDIM - 1);
    int k = idx >> 8;
    WT[(size_t)n * K + k] = __uint_as_float(f2tf32(W[(size_t)k * CDIM + n]));
}

// ---------------------------------------------------------------------------
// C[M,256] = (A[M,K] @ WT^T) * dinv[row]  — mma.sync tf32, cp.async pipeline
// ---------------------------------------------------------------------------
__global__ __launch_bounds__(256, 2) void gemm_mma_k(
    const float* __restrict__ A, const float* __restrict__ WT,
    float* __restrict__ C, int M, int K)
{
    __shared__ float As[2][BM * PITCH];
    __shared__ float Bs[2][BN * PITCH];

    const int tid  = threadIdx.x;
    const int lane = tid & 31;
    const int wid  = tid >> 5;
    const int wm   = wid & 1;
    const int wn   = wid >> 1;
    const int gq   = lane >> 2;
    const int cq   = lane & 3;
    const int row0 = blockIdx.y * BM;
    const int col0 = blockIdx.x * BN;

    const uint32_t asb = smem_u32(&As[0][0]);
    const uint32_t bsb = smem_u32(&Bs[0][0]);

    float acc[4][4][4];
    #pragma unroll
    for (int mt = 0; mt < 4; mt++)
        #pragma unroll
        for (int nt = 0; nt < 4; nt++)
            #pragma unroll
            for (int q = 0; q < 4; q++) acc[mt][nt][q] = 0.f;

    const int nkc = K / KCH;

    auto issue = [&](int kc, int buf) {
        const int koff = kc * KCH;
        #pragma unroll
        for (int t = 0; t < 2; t++) {
            int idx = tid + t * 256;          // 0..511 float4 slots
            int r   = idx >> 2;               // 0..127
            int kq  = (idx & 3) * 4;
            uint32_t soff = (uint32_t)((r * PITCH + kq) * 4) + (uint32_t)buf * BUFB;
            int gr = row0 + r;
            const float* srcA = A + (size_t)(gr < M ? gr : M - 1) * K + koff + kq;
            int nb = (gr < M) ? 16 : 0;
            asm volatile("cp.async.ca.shared.global [%0], [%1], 16, %2;"
                         :: "r"(asb + soff), "l"(srcA), "r"(nb));
            const float* srcB = WT + (size_t)(col0 + r) * K + koff + kq;
            asm volatile("cp.async.ca.shared.global [%0], [%1], 16;"
                         :: "r"(bsb + soff), "l"(srcB));
        }
        asm volatile("cp.async.commit_group;" ::: "memory");
    };

    issue(0, 0);

    for (int kc = 0; kc < nkc; kc++) {
        const int cur = kc & 1;
        const bool more = (kc + 1) < nkc;
        if (more) {
            issue(kc + 1, cur ^ 1);
            asm volatile("cp.async.wait_group 1;" ::: "memory");
        } else {
            asm volatile("cp.async.wait_group 0;" ::: "memory");
        }
        __syncthreads();

        #pragma unroll
        for (int k0 = 0; k0 < KCH; k0 += 8) {
            uint32_t bf[4][2];
            #pragma unroll
            for (int nt = 0; nt < 4; nt++) {
                int n = wn * 32 + nt * 8 + gq;
                bf[nt][0] = __float_as_uint(Bs[cur][n * PITCH + k0 + cq]);
                bf[nt][1] = __float_as_uint(Bs[cur][n * PITCH + k0 + cq + 4]);
            }
            #pragma unroll
            for (int mt = 0; mt < 4; mt++) {
                int r = wm * 64 + mt * 16 + gq;
                uint32_t af[4];
                af[0] = f2tf32(As[cur][(r    ) * PITCH + k0 + cq    ]);
                af[1] = f2tf32(As[cur][(r + 8) * PITCH + k0 + cq    ]);
                af[2] = f2tf32(As[cur][(r    ) * PITCH + k0 + cq + 4]);
                af[3] = f2tf32(As[cur][(r + 8) * PITCH + k0 + cq + 4]);
                #pragma unroll
                for (int nt = 0; nt < 4; nt++)
                    mma_tf32(acc[mt][nt], af, bf[nt]);
            }
        }
        __syncthreads();
    }

    #pragma unroll
    for (int mt = 0; mt < 4; mt++) {
        #pragma unroll
        for (int h = 0; h < 2; h++) {
            int row = row0 + wm * 64 + mt * 16 + gq + h * 8;
            if (row < M) {
                float s = g_dinv[row];
                float* cp = C + (size_t)row * CDIM + col0 + wn * 32;
                #pragma unroll
                for (int nt = 0; nt < 4; nt++) {
                    float2 o;
                    o.x = acc[mt][nt][h * 2 + 0] * s;
                    o.y = acc[mt][nt][h * 2 + 1] * s;
                    *reinterpret_cast<float2*>(cp + nt * 8 + cq * 2) = o;
                }
            }
        }
    }
}

// ---------------------------------------------------------------------------
// Fused CSR gather + self-loop + dinv[dst] + bias (+relu): 64 threads/node.
// ---------------------------------------------------------------------------
__global__ __launch_bounds__(256) void agg_k(const float* __restrict__ b,
                                             float* __restrict__ out, int relu)
{
    int node = blockIdx.x * 4 + (threadIdx.x >> 6);
    if (node >= NNODES) return;
    int lane = threadIdx.x & 63;

    const float4* hs4 = reinterpret_cast<const float4*>(g_hs);
    float4 acc = hs4[(size_t)node * 64 + lane];   // self loop (already *dinv[i])

    int j   = g_off[node];
    int end = g_off[node + 1];
    for (; j + 1 < end; j += 2) {
        int s0 = g_csrc[j];
        int s1 = g_csrc[j + 1];
        float4 v0 = hs4[(size_t)s0 * 64 + lane];
        float4 v1 = hs4[(size_t)s1 * 64 + lane];
        acc.x += v0.x; acc.y += v0.y; acc.z += v0.z; acc.w += v0.w;
        acc.x += v1.x; acc.y += v1.y; acc.z += v1.z; acc.w += v1.w;
    }
    if (j < end) {
        int s0 = g_csrc[j];
        float4 v0 = hs4[(size_t)s0 * 64 + lane];
        acc.x += v0.x; acc.y += v0.y; acc.z += v0.z; acc.w += v0.w;
    }

    float s = g_dinv[node];
    const float4 bb = *reinterpret_cast<const float4*>(b + lane * 4);
    float4 o;
    o.x = fmaf(acc.x, s, bb.x);
    o.y = fmaf(acc.y, s, bb.y);
    o.z = fmaf(acc.z, s, bb.z);
    o.w = fmaf(acc.w, s, bb.w);
    if (relu) {
        o.x = fmaxf(o.x, 0.f); o.y = fmaxf(o.y, 0.f);
        o.z = fmaxf(o.z, 0.f); o.w = fmaxf(o.w, 0.f);
    }
    reinterpret_cast<float4*>(out)[(size_t)node * 64 + lane] = o;
}

// ---------------------------------------------------------------------------
extern "C" void kernel_launch(void* const* d_in, const int* in_sizes, int n_in,
                              void* d_out, int out_size)
{
    const float* x  = (const float*)d_in[0];
    const int*   ei = (const int*)  d_in[1];
    const float* W1 = (const float*)d_in[2];
    const float* b1 = (const float*)d_in[3];
    const float* W2 = (const float*)d_in[4];
    const float* b2 = (const float*)d_in[5];
    (void)in_sizes; (void)n_in; (void)out_size;

    const int* src = ei;
    const int* dst = ei + NEDGES;

    float *hs, *h1, *wt1, *wt2;
    int* degp;
    cudaGetSymbolAddress((void**)&hs,  g_hs);
    cudaGetSymbolAddress((void**)&h1,  g_h1);
    cudaGetSymbolAddress((void**)&wt1, g_WT1);
    cudaGetSymbolAddress((void**)&wt2, g_WT2);
    cudaGetSymbolAddress((void**)&degp, g_deg);

    const dim3 gemm_grid(CDIM / BN, (NNODES + BM - 1) / BM);   // (2, 391)
    const int agg_grid = (NNODES + 3) / 4;

    transpose_tf32_k<<<(FIN * CDIM + 255) / 256, 256>>>(W1, wt1, FIN);
    transpose_tf32_k<<<(CDIM * CDIM + 255) / 256, 256>>>(W2, wt2, CDIM);
    zero_int_k<<<(NNODES + 255) / 256, 256>>>(degp, NNODES);
    degree_k  <<<(NEDGES / 4 + 255) / 256, 256>>>(dst, NEDGES / 4);
    dinv_k    <<<(NNODES + 255) / 256, 256>>>(NNODES);
    scan_k    <<<1, 1024>>>();
    csr_fill_k<<<(NEDGES + 255) / 256, 256>>>(src, dst, NEDGES);

    // layer 1
    gemm_mma_k<<<gemm_grid, 256>>>(x, wt1, hs, NNODES, FIN);
    agg_k     <<<agg_grid, 256>>>(b1, h1, 1);

    // layer 2
    gemm_mma_k<<<gemm_grid, 256>>>(h1, wt2, hs, NNODES, CDIM);
    agg_k     <<<agg_grid, 256>>>(b2, (float*)d_out, 0);
}